// round 11
// baseline (speedup 1.0000x reference)
#include <cuda_runtime.h>
#include <cuda_fp16.h>
#include <math.h>

#define BB   16
#define NN   1024
#define HH   4
#define KDIM 128
#define FO   64
#define COLS 256
#define ALPHA 0.2f
#define L2E   1.44269504088896340736f
#define MAXNZ 160

// Static device scratch
__device__ __half g_hh4[BB*NN*COLS];   // h fp16, lane-interleaved for k4, 8 MB
// layout: halfs [row][lane(0..31)][h(0..3)][po(0..1)], value = h[row][h*64 + po*32 + lane]
__device__ float4 g_f1q[BB*NN], g_f2q[BB*NN];   // per-(b,n) head-packed f1/f2
__device__ float4 g_part[8][BB*NN];
__device__ float4 g_invq[BB*NN];
__device__ int    g_sj[(size_t)BB*NN*MAXNZ];    // per-row compacted j lists
__device__ int    g_cnt[BB*NN];

__device__ __forceinline__ float ex2f(float x) {
    float y; asm("ex2.approx.f32 %0, %1;" : "=f"(y) : "f"(x)); return y;
}
__device__ __forceinline__ void ffma2(unsigned long long& d,
                                      unsigned long long a, unsigned long long b) {
    asm("fma.rn.f32x2 %0, %1, %2, %0;" : "+l"(d) : "l"(a), "l"(b));
}
__device__ __forceinline__ float2 unpk(unsigned long long p) {
    float2 r;
    asm("mov.b64 {%0, %1}, %2;" : "=f"(r.x), "=f"(r.y) : "l"(p));
    return r;
}

// ---------------------------------------------------------------------------
// K1: FFMA2 GEMM + fused f1/f2 reduction (unchanged R10 winner).
// ---------------------------------------------------------------------------
__global__ void __launch_bounds__(256, 1) k1_gemm(
        const float* __restrict__ x, const float* __restrict__ SE,
        const float* __restrict__ W,
        const float* __restrict__ a1, const float* __restrict__ a2) {
    __shared__ __align__(16) float As[128][36];
    __shared__ __align__(16) float Bs[64][36];
    const int rt = blockIdx.x, ct = blockIdx.y, tid = threadIdx.x;
    const int tx = tid & 15, ty = tid >> 4;

    unsigned long long acc[8][4];
#pragma unroll
    for (int r = 0; r < 8; r++)
#pragma unroll
        for (int c = 0; c < 4; c++) acc[r][c] = 0ull;

    for (int ch = 0; ch < 4; ch++) {
        const int kk = ch * 32;
#pragma unroll
        for (int r = 0; r < 4; r++) {
            int q = tid + r * 256;
            int m = q >> 3, kc = (q & 7) << 2;
            int nb = rt * 128 + m;
            const float* src = (kk < 64)
                ? (x  + (size_t)nb * 64 + kk + kc)
                : (SE + (size_t)(nb & 1023) * 64 + (kk - 64) + kc);
            *(float4*)&As[m][kc] = *(const float4*)src;
        }
#pragma unroll
        for (int r = 0; r < 2; r++) {
            int q = tid + r * 256;
            int c = q & 63, k4 = (q >> 6) << 2;
            float4 v;
            const float* wp = W + ((size_t)ct * KDIM + kk + k4) * FO + c;
            v.x = wp[0]; v.y = wp[FO]; v.z = wp[2 * FO]; v.w = wp[3 * FO];
            *(float4*)&Bs[c][k4] = v;
        }
        __syncthreads();
#pragma unroll
        for (int kq = 0; kq < 8; kq++) {
            ulonglong2 bq[4];
#pragma unroll
            for (int c = 0; c < 4; c++)
                bq[c] = *(const ulonglong2*)&Bs[tx + 16 * c][kq * 4];
#pragma unroll
            for (int r = 0; r < 8; r++) {
                ulonglong2 aq = *(const ulonglong2*)&As[ty * 8 + r][kq * 4];
#pragma unroll
                for (int c = 0; c < 4; c++) {
                    ffma2(acc[r][c], aq.x, bq[c].x);
                    ffma2(acc[r][c], aq.y, bq[c].y);
                }
            }
        }
        __syncthreads();
    }

    const int row0 = rt * 128 + ty * 8;
    const float A0 = a1[ct * FO + tx],      A1 = a1[ct * FO + tx + 16];
    const float A2 = a1[ct * FO + tx + 32], A3 = a1[ct * FO + tx + 48];
    const float B0 = a2[ct * FO + tx],      B1 = a2[ct * FO + tx + 16];
    const float B2 = a2[ct * FO + tx + 32], B3 = a2[ct * FO + tx + 48];
    float p1[8], p2[8];
#pragma unroll
    for (int r = 0; r < 8; r++) {
        float2 q0 = unpk(acc[r][0]);
        float2 q1 = unpk(acc[r][1]);
        float2 q2 = unpk(acc[r][2]);
        float2 q3 = unpk(acc[r][3]);
        float v0 = q0.x + q0.y;
        float v1 = q1.x + q1.y;
        float v2 = q2.x + q2.y;
        float v3 = q3.x + q3.y;
        size_t row = (size_t)(row0 + r);
        __half2* dst = (__half2*)(g_hh4 + row * COLS);
        dst[tx * 4 + ct]        = __floats2half2_rn(v0, v2);
        dst[(tx + 16) * 4 + ct] = __floats2half2_rn(v1, v3);
        p1[r] = v0 * A0 + v1 * A1 + v2 * A2 + v3 * A3;
        p2[r] = v0 * B0 + v1 * B1 + v2 * B2 + v3 * B3;
    }
#pragma unroll
    for (int mask = 1; mask < 16; mask <<= 1) {
#pragma unroll
        for (int r = 0; r < 8; r++) {
            p1[r] += __shfl_xor_sync(0xffffffffu, p1[r], mask);
            p2[r] += __shfl_xor_sync(0xffffffffu, p2[r], mask);
        }
    }
    if (tx == 0) {
#pragma unroll
        for (int r = 0; r < 8; r++) {
            ((float*)g_f1q)[(size_t)(row0 + r) * 4 + ct] = p1[r];
            ((float*)g_f2q)[(size_t)(row0 + r) * 4 + ct] = p2[r];
        }
    }
}

// ---------------------------------------------------------------------------
// K3 v2: 1024 interleaved blocks.
//  even bid: dense partial column sums (unchanged math)
//  odd  bid: adjacency compaction (DRAM-bound; hides under k3 compute)
// ---------------------------------------------------------------------------
__global__ void k3(const float* __restrict__ P_l, const float* __restrict__ adj) {
    __shared__ float4 sf1[128], sar[128];
    const int bid = blockIdx.x;
    const int tid = threadIdx.x;

    if (bid & 1) {
        // ---- adjacency compaction: 512 blocks x 8 warps x 4 rows ----
        const int cb = bid >> 1;                 // 0..511
        const int ws = tid >> 5, lane = tid & 31;
#pragma unroll
        for (int rr = 0; rr < 4; rr++) {
            const int row = cb * 32 + ws * 4 + rr;
            const float* adjrow = adj + (size_t)row * NN;
            float4 av[8];
#pragma unroll
            for (int q = 0; q < 8; q++)
                av[q] = *(const float4*)(adjrow + q * 128 + lane * 4);
            int base = 0;
#pragma unroll
            for (int q = 0; q < 8; q++) {
                float vv[4] = {av[q].x, av[q].y, av[q].z, av[q].w};
#pragma unroll
                for (int u = 0; u < 4; u++) {
                    unsigned m = __ballot_sync(0xffffffffu, vv[u] != 0.f);
                    if (vv[u] != 0.f) {
                        int pos = base + __popc(m & ((1u << lane) - 1));
                        if (pos < MAXNZ)
                            g_sj[(size_t)row * MAXNZ + pos] = q * 128 + lane * 4 + u;
                    }
                    base += __popc(m);
                }
            }
            if (lane == 0) g_cnt[row] = min(base, MAXNZ);
        }
        return;
    }

    // ---- dense partial sums (identical to R10) ----
    const int cb = bid >> 1;                     // 0..511
    const int ic = cb & 7, jt = (cb >> 3) & 3, b = cb >> 5;
    if (tid < 128) {
        sf1[tid] = g_f1q[b * NN + ic * 128 + tid];
    } else {
        int ii = tid - 128;
        float4 f1 = g_f1q[b * NN + ic * 128 + ii];
        float4 a;
        a.x = ALPHA * L2E * (P_l[0]*f1.x + P_l[4]*f1.y + P_l[8]*f1.z  + P_l[12]*f1.w);
        a.y = ALPHA * L2E * (P_l[1]*f1.x + P_l[5]*f1.y + P_l[9]*f1.z  + P_l[13]*f1.w);
        a.z = ALPHA * L2E * (P_l[2]*f1.x + P_l[6]*f1.y + P_l[10]*f1.z + P_l[14]*f1.w);
        a.w = ALPHA * L2E * (P_l[3]*f1.x + P_l[7]*f1.y + P_l[11]*f1.z + P_l[15]*f1.w);
        sar[ii] = a;
    }
    __syncthreads();

    const int j = jt * 256 + tid;
    const float4 f2 = g_f2q[b * NN + j];
    float c[16];
#pragma unroll
    for (int t = 0; t < 16; t++) c[t] = (1.f - ALPHA) * L2E * P_l[t];

    float s0 = 0.f, s1 = 0.f, s2 = 0.f, s3 = 0.f;
#pragma unroll 4
    for (int i = 0; i < 128; i++) {
        float4 f1 = sf1[i], ar = sar[i];
        float r0 = fmaxf(f1.x + f2.x, 0.f);
        float r1 = fmaxf(f1.y + f2.y, 0.f);
        float r2 = fmaxf(f1.z + f2.z, 0.f);
        float r3 = fmaxf(f1.w + f2.w, 0.f);
        float e0 = ar.x, e1 = ar.y, e2 = ar.z, e3 = ar.w;
        e0 = fmaf(c[0], r0, e0); e0 = fmaf(c[4], r1, e0); e0 = fmaf(c[8],  r2, e0); e0 = fmaf(c[12], r3, e0);
        e1 = fmaf(c[1], r0, e1); e1 = fmaf(c[5], r1, e1); e1 = fmaf(c[9],  r2, e1); e1 = fmaf(c[13], r3, e1);
        e2 = fmaf(c[2], r0, e2); e2 = fmaf(c[6], r1, e2); e2 = fmaf(c[10], r2, e2); e2 = fmaf(c[14], r3, e2);
        e3 = fmaf(c[3], r0, e3); e3 = fmaf(c[7], r1, e3); e3 = fmaf(c[11], r2, e3); e3 = fmaf(c[15], r3, e3);
        s0 += ex2f(e0); s1 += ex2f(e1); s2 += ex2f(e2); s3 += ex2f(e3);
    }
    g_part[ic][b * NN + j] = make_float4(s0, s1, s2, s3);
}

// K3b: serial reduce (unchanged)
__global__ void k3b() {
    int bj = blockIdx.x * 256 + threadIdx.x;
    float4 s = g_part[0][bj];
#pragma unroll
    for (int ic = 1; ic < 8; ic++) {
        float4 p = g_part[ic][bj];
        s.x += p.x; s.y += p.y; s.z += p.z; s.w += p.w;
    }
    g_invq[bj] = make_float4(1.f / s.x, 1.f / s.y, 1.f / s.z, 1.f / s.w);
}

// ---------------------------------------------------------------------------
// K4 v8: no phase A — j-lists precompacted (fewer regs, no adj read).
// ---------------------------------------------------------------------------
__global__ void __launch_bounds__(256) k4(
        const float* __restrict__ x,
        const float* __restrict__ P_l, const float* __restrict__ P_w,
        float* __restrict__ out) {
    __shared__ int    sj[8][MAXNZ];
    __shared__ float4 sw[8][MAXNZ];
    const int ws   = threadIdx.x >> 5;
    const int lane = threadIdx.x & 31;
    const int gw   = blockIdx.x * 8 + ws;
    const int b = gw >> 10, i = gw & 1023;
    const int bN = b * NN;

    const int nnz = g_cnt[gw];

    // Phase B: lane-parallel weights; j from precompacted list (coalesced)
    {
        const float4 f1 = g_f1q[bN + i];
        float c[16], pw[16];
#pragma unroll
        for (int t = 0; t < 16; t++) { c[t] = (1.f - ALPHA) * L2E * P_l[t]; pw[t] = P_w[t]; }
        const float ar0 = 0.25f * (c[0]*f1.x + c[4]*f1.y + c[8]*f1.z  + c[12]*f1.w);
        const float ar1 = 0.25f * (c[1]*f1.x + c[5]*f1.y + c[9]*f1.z  + c[13]*f1.w);
        const float ar2 = 0.25f * (c[2]*f1.x + c[6]*f1.y + c[10]*f1.z + c[14]*f1.w);
        const float ar3 = 0.25f * (c[3]*f1.x + c[7]*f1.y + c[11]*f1.z + c[15]*f1.w);
        const int* sjrow = g_sj + (size_t)gw * MAXNZ;
        for (int t = lane; t < nnz; t += 32) {
            int j = sjrow[t];
            sj[ws][t] = j;
            float4 f2  = g_f2q[bN + j];
            float4 inv = g_invq[bN + j];
            float r0 = fmaxf(f1.x + f2.x, 0.f);
            float r1 = fmaxf(f1.y + f2.y, 0.f);
            float r2 = fmaxf(f1.z + f2.z, 0.f);
            float r3 = fmaxf(f1.w + f2.w, 0.f);
            float e0 = ar0, e1 = ar1, e2 = ar2, e3 = ar3;
            e0 = fmaf(c[0], r0, e0); e0 = fmaf(c[4], r1, e0); e0 = fmaf(c[8],  r2, e0); e0 = fmaf(c[12], r3, e0);
            e1 = fmaf(c[1], r0, e1); e1 = fmaf(c[5], r1, e1); e1 = fmaf(c[9],  r2, e1); e1 = fmaf(c[13], r3, e1);
            e2 = fmaf(c[2], r0, e2); e2 = fmaf(c[6], r1, e2); e2 = fmaf(c[10], r2, e2); e2 = fmaf(c[14], r3, e2);
            e3 = fmaf(c[3], r0, e3); e3 = fmaf(c[7], r1, e3); e3 = fmaf(c[11], r2, e3); e3 = fmaf(c[15], r3, e3);
            float x0 = ex2f(e0) * inv.x;
            float x1 = ex2f(e1) * inv.y;
            float x2 = ex2f(e2) * inv.z;
            float x3 = ex2f(e3) * inv.w;
            float w0 = pw[0]*x0 + pw[4]*x1 + pw[8]*x2  + pw[12]*x3;
            float w1 = pw[1]*x0 + pw[5]*x1 + pw[9]*x2  + pw[13]*x3;
            float w2 = pw[2]*x0 + pw[6]*x1 + pw[10]*x2 + pw[14]*x3;
            float w3 = pw[3]*x0 + pw[7]*x1 + pw[11]*x2 + pw[15]*x3;
            sw[ws][t] = make_float4(w0, w1, w2, w3);
        }
    }
    __syncwarp();

    // Phase C: interleaved fp16 gather, ONE LDG.128 per nnz, unroll 8
    float2 acc[4];
#pragma unroll
    for (int m = 0; m < 4; m++) acc[m] = make_float2(0.f, 0.f);

    const __half* hbase = g_hh4 + (size_t)bN * COLS + lane * 8;
    int t = 0;
    for (; t + 8 <= nnz; t += 8) {
#pragma unroll
        for (int u = 0; u < 8; u++) {
            int j = sj[ws][t + u];
            float4 w = sw[ws][t + u];
            uint4 u4 = *(const uint4*)(hbase + (size_t)j * COLS);
            float2 v0 = __half22float2(*(__half2*)&u4.x);
            float2 v1 = __half22float2(*(__half2*)&u4.y);
            float2 v2 = __half22float2(*(__half2*)&u4.z);
            float2 v3 = __half22float2(*(__half2*)&u4.w);
            acc[0].x = fmaf(w.x, v0.x, acc[0].x); acc[0].y = fmaf(w.x, v0.y, acc[0].y);
            acc[1].x = fmaf(w.y, v1.x, acc[1].x); acc[1].y = fmaf(w.y, v1.y, acc[1].y);
            acc[2].x = fmaf(w.z, v2.x, acc[2].x); acc[2].y = fmaf(w.z, v2.y, acc[2].y);
            acc[3].x = fmaf(w.w, v3.x, acc[3].x); acc[3].y = fmaf(w.w, v3.y, acc[3].y);
        }
    }
    for (; t < nnz; t++) {
        int j = sj[ws][t];
        float4 w = sw[ws][t];
        uint4 u4 = *(const uint4*)(hbase + (size_t)j * COLS);
        float2 v0 = __half22float2(*(__half2*)&u4.x);
        float2 v1 = __half22float2(*(__half2*)&u4.y);
        float2 v2 = __half22float2(*(__half2*)&u4.z);
        float2 v3 = __half22float2(*(__half2*)&u4.w);
        acc[0].x = fmaf(w.x, v0.x, acc[0].x); acc[0].y = fmaf(w.x, v0.y, acc[0].y);
        acc[1].x = fmaf(w.y, v1.x, acc[1].x); acc[1].y = fmaf(w.y, v1.y, acc[1].y);
        acc[2].x = fmaf(w.z, v2.x, acc[2].x); acc[2].y = fmaf(w.z, v2.y, acc[2].y);
        acc[3].x = fmaf(w.w, v3.x, acc[3].x); acc[3].y = fmaf(w.w, v3.y, acc[3].y);
    }

    // Epilogue: residual + ELU. acc[h] = (col h*64+lane, col h*64+32+lane).
    const float* xrow = x + (size_t)(bN + i) * FO;
    float xv0 = xrow[lane], xv1 = xrow[lane + 32];
    float* orow = out + (size_t)(bN + i) * COLS;
#pragma unroll
    for (int m = 0; m < 4; m++) {
        float z0 = acc[m].x + xv0;
        float z1 = acc[m].y + xv1;
        orow[m * 64 + lane]      = (z0 > 0.f) ? z0 : expm1f(z0);
        orow[m * 64 + 32 + lane] = (z1 > 0.f) ? z1 : expm1f(z1);
    }
}

extern "C" void kernel_launch(void* const* d_in, const int* in_sizes, int n_in,
                              void* d_out, int out_size) {
    const float* x   = (const float*)d_in[0];
    const float* adj = (const float*)d_in[1];
    const float* SE  = (const float*)d_in[2];
    const float* W   = (const float*)d_in[3];
    const float* a1  = (const float*)d_in[4];
    const float* a2  = (const float*)d_in[5];
    const float* P_l = (const float*)d_in[6];
    const float* P_w = (const float*)d_in[7];
    float* out = (float*)d_out;

    k1_gemm<<<dim3(128, 4), 256>>>(x, SE, W, a1, a2);
    k3<<<1024, 256>>>(P_l, adj);
    k3b<<<64, 256>>>();
    k4<<<2048, 256>>>(x, P_l, P_w, out);
}

// round 12
// speedup vs baseline: 1.0163x; 1.0163x over previous
#include <cuda_runtime.h>
#include <cuda_fp16.h>
#include <math.h>

#define BB   16
#define NN   1024
#define HH   4
#define KDIM 128
#define FO   64
#define COLS 256
#define ALPHA 0.2f
#define L2E   1.44269504088896340736f
#define MAXNZ 160

// Static device scratch
__device__ __half g_hh4[BB*NN*COLS];   // h fp16, lane-interleaved for k4, 8 MB
// layout: halfs [row][lane(0..31)][h(0..3)][po(0..1)], value = h[row][h*64 + po*32 + lane]
__device__ float4 g_f1q[BB*NN], g_f2q[BB*NN];   // per-(b,n) head-packed f1/f2
__device__ float4 g_part[8][BB*NN];
__device__ float4 g_invq[BB*NN];

__device__ __forceinline__ float ex2f(float x) {
    float y; asm("ex2.approx.f32 %0, %1;" : "=f"(y) : "f"(x)); return y;
}
__device__ __forceinline__ void ffma2(unsigned long long& d,
                                      unsigned long long a, unsigned long long b) {
    asm("fma.rn.f32x2 %0, %1, %2, %0;" : "+l"(d) : "l"(a), "l"(b));
}
__device__ __forceinline__ float2 unpk(unsigned long long p) {
    float2 r;
    asm("mov.b64 {%0, %1}, %2;" : "=f"(r.x), "=f"(r.y) : "l"(p));
    return r;
}

// ---------------------------------------------------------------------------
// K1: FFMA2 GEMM + fused f1/f2 reduction (unchanged R10 winner).
// ---------------------------------------------------------------------------
__global__ void __launch_bounds__(256, 1) k1_gemm(
        const float* __restrict__ x, const float* __restrict__ SE,
        const float* __restrict__ W,
        const float* __restrict__ a1, const float* __restrict__ a2) {
    __shared__ __align__(16) float As[128][36];
    __shared__ __align__(16) float Bs[64][36];
    const int rt = blockIdx.x, ct = blockIdx.y, tid = threadIdx.x;
    const int tx = tid & 15, ty = tid >> 4;

    unsigned long long acc[8][4];
#pragma unroll
    for (int r = 0; r < 8; r++)
#pragma unroll
        for (int c = 0; c < 4; c++) acc[r][c] = 0ull;

    for (int ch = 0; ch < 4; ch++) {
        const int kk = ch * 32;
#pragma unroll
        for (int r = 0; r < 4; r++) {
            int q = tid + r * 256;
            int m = q >> 3, kc = (q & 7) << 2;
            int nb = rt * 128 + m;
            const float* src = (kk < 64)
                ? (x  + (size_t)nb * 64 + kk + kc)
                : (SE + (size_t)(nb & 1023) * 64 + (kk - 64) + kc);
            *(float4*)&As[m][kc] = *(const float4*)src;
        }
#pragma unroll
        for (int r = 0; r < 2; r++) {
            int q = tid + r * 256;
            int c = q & 63, k4 = (q >> 6) << 2;
            float4 v;
            const float* wp = W + ((size_t)ct * KDIM + kk + k4) * FO + c;
            v.x = wp[0]; v.y = wp[FO]; v.z = wp[2 * FO]; v.w = wp[3 * FO];
            *(float4*)&Bs[c][k4] = v;
        }
        __syncthreads();
#pragma unroll
        for (int kq = 0; kq < 8; kq++) {
            ulonglong2 bq[4];
#pragma unroll
            for (int c = 0; c < 4; c++)
                bq[c] = *(const ulonglong2*)&Bs[tx + 16 * c][kq * 4];
#pragma unroll
            for (int r = 0; r < 8; r++) {
                ulonglong2 aq = *(const ulonglong2*)&As[ty * 8 + r][kq * 4];
#pragma unroll
                for (int c = 0; c < 4; c++) {
                    ffma2(acc[r][c], aq.x, bq[c].x);
                    ffma2(acc[r][c], aq.y, bq[c].y);
                }
            }
        }
        __syncthreads();
    }

    const int row0 = rt * 128 + ty * 8;
    const float A0 = a1[ct * FO + tx],      A1 = a1[ct * FO + tx + 16];
    const float A2 = a1[ct * FO + tx + 32], A3 = a1[ct * FO + tx + 48];
    const float B0 = a2[ct * FO + tx],      B1 = a2[ct * FO + tx + 16];
    const float B2 = a2[ct * FO + tx + 32], B3 = a2[ct * FO + tx + 48];
    float p1[8], p2[8];
#pragma unroll
    for (int r = 0; r < 8; r++) {
        float2 q0 = unpk(acc[r][0]);
        float2 q1 = unpk(acc[r][1]);
        float2 q2 = unpk(acc[r][2]);
        float2 q3 = unpk(acc[r][3]);
        float v0 = q0.x + q0.y;
        float v1 = q1.x + q1.y;
        float v2 = q2.x + q2.y;
        float v3 = q3.x + q3.y;
        size_t row = (size_t)(row0 + r);
        __half2* dst = (__half2*)(g_hh4 + row * COLS);
        dst[tx * 4 + ct]        = __floats2half2_rn(v0, v2);
        dst[(tx + 16) * 4 + ct] = __floats2half2_rn(v1, v3);
        p1[r] = v0 * A0 + v1 * A1 + v2 * A2 + v3 * A3;
        p2[r] = v0 * B0 + v1 * B1 + v2 * B2 + v3 * B3;
    }
#pragma unroll
    for (int mask = 1; mask < 16; mask <<= 1) {
#pragma unroll
        for (int r = 0; r < 8; r++) {
            p1[r] += __shfl_xor_sync(0xffffffffu, p1[r], mask);
            p2[r] += __shfl_xor_sync(0xffffffffu, p2[r], mask);
        }
    }
    if (tx == 0) {
#pragma unroll
        for (int r = 0; r < 8; r++) {
            ((float*)g_f1q)[(size_t)(row0 + r) * 4 + ct] = p1[r];
            ((float*)g_f2q)[(size_t)(row0 + r) * 4 + ct] = p2[r];
        }
    }
}

// ---------------------------------------------------------------------------
// K3: partial column sums; sar computed in the prologue from f1q (R10 form).
// ---------------------------------------------------------------------------
__global__ void k3(const float* __restrict__ P_l) {
    const int ic = blockIdx.x, jt = blockIdx.y, b = blockIdx.z;
    __shared__ float4 sf1[128], sar[128];
    const int tid = threadIdx.x;
    if (tid < 128) {
        sf1[tid] = g_f1q[b * NN + ic * 128 + tid];
    } else {
        int ii = tid - 128;
        float4 f1 = g_f1q[b * NN + ic * 128 + ii];
        float4 a;
        a.x = ALPHA * L2E * (P_l[0]*f1.x + P_l[4]*f1.y + P_l[8]*f1.z  + P_l[12]*f1.w);
        a.y = ALPHA * L2E * (P_l[1]*f1.x + P_l[5]*f1.y + P_l[9]*f1.z  + P_l[13]*f1.w);
        a.z = ALPHA * L2E * (P_l[2]*f1.x + P_l[6]*f1.y + P_l[10]*f1.z + P_l[14]*f1.w);
        a.w = ALPHA * L2E * (P_l[3]*f1.x + P_l[7]*f1.y + P_l[11]*f1.z + P_l[15]*f1.w);
        sar[ii] = a;
    }
    __syncthreads();

    const int j = jt * 256 + tid;
    const float4 f2 = g_f2q[b * NN + j];
    float c[16];
#pragma unroll
    for (int t = 0; t < 16; t++) c[t] = (1.f - ALPHA) * L2E * P_l[t];

    float s0 = 0.f, s1 = 0.f, s2 = 0.f, s3 = 0.f;
#pragma unroll 4
    for (int i = 0; i < 128; i++) {
        float4 f1 = sf1[i], ar = sar[i];
        float r0 = fmaxf(f1.x + f2.x, 0.f);
        float r1 = fmaxf(f1.y + f2.y, 0.f);
        float r2 = fmaxf(f1.z + f2.z, 0.f);
        float r3 = fmaxf(f1.w + f2.w, 0.f);
        float e0 = ar.x, e1 = ar.y, e2 = ar.z, e3 = ar.w;
        e0 = fmaf(c[0], r0, e0); e0 = fmaf(c[4], r1, e0); e0 = fmaf(c[8],  r2, e0); e0 = fmaf(c[12], r3, e0);
        e1 = fmaf(c[1], r0, e1); e1 = fmaf(c[5], r1, e1); e1 = fmaf(c[9],  r2, e1); e1 = fmaf(c[13], r3, e1);
        e2 = fmaf(c[2], r0, e2); e2 = fmaf(c[6], r1, e2); e2 = fmaf(c[10], r2, e2); e2 = fmaf(c[14], r3, e2);
        e3 = fmaf(c[3], r0, e3); e3 = fmaf(c[7], r1, e3); e3 = fmaf(c[11], r2, e3); e3 = fmaf(c[15], r3, e3);
        s0 += ex2f(e0); s1 += ex2f(e1); s2 += ex2f(e2); s3 += ex2f(e3);
    }
    g_part[ic][b * NN + j] = make_float4(s0, s1, s2, s3);
}

// K3b: serial reduce (unchanged)
__global__ void k3b() {
    int bj = blockIdx.x * 256 + threadIdx.x;
    float4 s = g_part[0][bj];
#pragma unroll
    for (int ic = 1; ic < 8; ic++) {
        float4 p = g_part[ic][bj];
        s.x += p.x; s.y += p.y; s.z += p.z; s.w += p.w;
    }
    g_invq[bj] = make_float4(1.f / s.x, 1.f / s.y, 1.f / s.z, 1.f / s.w);
}

// ---------------------------------------------------------------------------
// K4 v9: R10 structure, register diet for occupancy:
//  - c[]/pw[] constants in SHARED (LDS broadcast) instead of 32 registers
//  - phase A adj preload in 2 halves (av[4] x2)
//  - phase C unroll 4
//  - __launch_bounds__(256, 5) -> 51-reg target, 5 blocks/SM
// ---------------------------------------------------------------------------
__global__ void __launch_bounds__(256, 5) k4(
        const float* __restrict__ x, const float* __restrict__ adj,
        const float* __restrict__ P_l, const float* __restrict__ P_w,
        float* __restrict__ out) {
    __shared__ int    sj[8][MAXNZ];
    __shared__ float4 sw[8][MAXNZ];
    __shared__ float  sc[16], spw[16];
    const int ws   = threadIdx.x >> 5;
    const int lane = threadIdx.x & 31;
    const int gw   = blockIdx.x * 8 + ws;
    const int b = gw >> 10, i = gw & 1023;
    const int bN = b * NN;

    if (threadIdx.x < 16)       sc[threadIdx.x]        = (1.f - ALPHA) * L2E * P_l[threadIdx.x];
    else if (threadIdx.x < 32)  spw[threadIdx.x - 16]  = P_w[threadIdx.x - 16];

    // Phase A: adj row in 2 halves (4 LDG.128 in flight each), register ballots
    const float* adjrow = adj + (size_t)(bN + i) * NN;
    int base = 0;
#pragma unroll
    for (int hlf = 0; hlf < 2; hlf++) {
        float4 av[4];
#pragma unroll
        for (int q = 0; q < 4; q++)
            av[q] = *(const float4*)(adjrow + (hlf * 4 + q) * 128 + lane * 4);
#pragma unroll
        for (int q = 0; q < 4; q++) {
            float vv[4] = {av[q].x, av[q].y, av[q].z, av[q].w};
#pragma unroll
            for (int u = 0; u < 4; u++) {
                unsigned m = __ballot_sync(0xffffffffu, vv[u] != 0.f);
                if (vv[u] != 0.f) {
                    int pos = base + __popc(m & ((1u << lane) - 1));
                    if (pos < MAXNZ) sj[ws][pos] = (hlf * 4 + q) * 128 + lane * 4 + u;
                }
                base += __popc(m);
            }
        }
    }
    int nnz = min(base, MAXNZ);
    __syncthreads();   // sj visible (warp-local) + sc/spw visible block-wide

    // Phase B: lane-parallel weights (constants via LDS broadcast)
    {
        const float4 f1 = g_f1q[bN + i];
        const float ar0 = 0.25f * (sc[0]*f1.x + sc[4]*f1.y + sc[8]*f1.z  + sc[12]*f1.w);
        const float ar1 = 0.25f * (sc[1]*f1.x + sc[5]*f1.y + sc[9]*f1.z  + sc[13]*f1.w);
        const float ar2 = 0.25f * (sc[2]*f1.x + sc[6]*f1.y + sc[10]*f1.z + sc[14]*f1.w);
        const float ar3 = 0.25f * (sc[3]*f1.x + sc[7]*f1.y + sc[11]*f1.z + sc[15]*f1.w);
        for (int t = lane; t < nnz; t += 32) {
            int j = sj[ws][t];
            float4 f2  = g_f2q[bN + j];
            float4 inv = g_invq[bN + j];
            float r0 = fmaxf(f1.x + f2.x, 0.f);
            float r1 = fmaxf(f1.y + f2.y, 0.f);
            float r2 = fmaxf(f1.z + f2.z, 0.f);
            float r3 = fmaxf(f1.w + f2.w, 0.f);
            float e0 = ar0, e1 = ar1, e2 = ar2, e3 = ar3;
            e0 = fmaf(sc[0], r0, e0); e0 = fmaf(sc[4], r1, e0); e0 = fmaf(sc[8],  r2, e0); e0 = fmaf(sc[12], r3, e0);
            e1 = fmaf(sc[1], r0, e1); e1 = fmaf(sc[5], r1, e1); e1 = fmaf(sc[9],  r2, e1); e1 = fmaf(sc[13], r3, e1);
            e2 = fmaf(sc[2], r0, e2); e2 = fmaf(sc[6], r1, e2); e2 = fmaf(sc[10], r2, e2); e2 = fmaf(sc[14], r3, e2);
            e3 = fmaf(sc[3], r0, e3); e3 = fmaf(sc[7], r1, e3); e3 = fmaf(sc[11], r2, e3); e3 = fmaf(sc[15], r3, e3);
            float x0 = ex2f(e0) * inv.x;
            float x1 = ex2f(e1) * inv.y;
            float x2 = ex2f(e2) * inv.z;
            float x3 = ex2f(e3) * inv.w;
            float w0 = spw[0]*x0 + spw[4]*x1 + spw[8]*x2  + spw[12]*x3;
            float w1 = spw[1]*x0 + spw[5]*x1 + spw[9]*x2  + spw[13]*x3;
            float w2 = spw[2]*x0 + spw[6]*x1 + spw[10]*x2 + spw[14]*x3;
            float w3 = spw[3]*x0 + spw[7]*x1 + spw[11]*x2 + spw[15]*x3;
            sw[ws][t] = make_float4(w0, w1, w2, w3);
        }
    }
    __syncwarp();

    // Phase C: interleaved fp16 gather, ONE LDG.128 per nnz, unroll 4
    float2 acc[4];
#pragma unroll
    for (int m = 0; m < 4; m++) acc[m] = make_float2(0.f, 0.f);

    const __half* hbase = g_hh4 + (size_t)bN * COLS + lane * 8;
    int t = 0;
    for (; t + 4 <= nnz; t += 4) {
#pragma unroll
        for (int u = 0; u < 4; u++) {
            int j = sj[ws][t + u];
            float4 w = sw[ws][t + u];
            uint4 u4 = *(const uint4*)(hbase + (size_t)j * COLS);
            float2 v0 = __half22float2(*(__half2*)&u4.x);
            float2 v1 = __half22float2(*(__half2*)&u4.y);
            float2 v2 = __half22float2(*(__half2*)&u4.z);
            float2 v3 = __half22float2(*(__half2*)&u4.w);
            acc[0].x = fmaf(w.x, v0.x, acc[0].x); acc[0].y = fmaf(w.x, v0.y, acc[0].y);
            acc[1].x = fmaf(w.y, v1.x, acc[1].x); acc[1].y = fmaf(w.y, v1.y, acc[1].y);
            acc[2].x = fmaf(w.z, v2.x, acc[2].x); acc[2].y = fmaf(w.z, v2.y, acc[2].y);
            acc[3].x = fmaf(w.w, v3.x, acc[3].x); acc[3].y = fmaf(w.w, v3.y, acc[3].y);
        }
    }
    for (; t < nnz; t++) {
        int j = sj[ws][t];
        float4 w = sw[ws][t];
        uint4 u4 = *(const uint4*)(hbase + (size_t)j * COLS);
        float2 v0 = __half22float2(*(__half2*)&u4.x);
        float2 v1 = __half22float2(*(__half2*)&u4.y);
        float2 v2 = __half22float2(*(__half2*)&u4.z);
        float2 v3 = __half22float2(*(__half2*)&u4.w);
        acc[0].x = fmaf(w.x, v0.x, acc[0].x); acc[0].y = fmaf(w.x, v0.y, acc[0].y);
        acc[1].x = fmaf(w.y, v1.x, acc[1].x); acc[1].y = fmaf(w.y, v1.y, acc[1].y);
        acc[2].x = fmaf(w.z, v2.x, acc[2].x); acc[2].y = fmaf(w.z, v2.y, acc[2].y);
        acc[3].x = fmaf(w.w, v3.x, acc[3].x); acc[3].y = fmaf(w.w, v3.y, acc[3].y);
    }

    // Epilogue: residual + ELU. acc[h] = (col h*64+lane, col h*64+32+lane).
    const float* xrow = x + (size_t)(bN + i) * FO;
    float xv0 = xrow[lane], xv1 = xrow[lane + 32];
    float* orow = out + (size_t)(bN + i) * COLS;
#pragma unroll
    for (int m = 0; m < 4; m++) {
        float z0 = acc[m].x + xv0;
        float z1 = acc[m].y + xv1;
        orow[m * 64 + lane]      = (z0 > 0.f) ? z0 : expm1f(z0);
        orow[m * 64 + 32 + lane] = (z1 > 0.f) ? z1 : expm1f(z1);
    }
}

extern "C" void kernel_launch(void* const* d_in, const int* in_sizes, int n_in,
                              void* d_out, int out_size) {
    const float* x   = (const float*)d_in[0];
    const float* adj = (const float*)d_in[1];
    const float* SE  = (const float*)d_in[2];
    const float* W   = (const float*)d_in[3];
    const float* a1  = (const float*)d_in[4];
    const float* a2  = (const float*)d_in[5];
    const float* P_l = (const float*)d_in[6];
    const float* P_w = (const float*)d_in[7];
    float* out = (float*)d_out;

    k1_gemm<<<dim3(128, 4), 256>>>(x, SE, W, a1, a2);
    k3<<<dim3(8, 4, 16), 256>>>(P_l);
    k3b<<<64, 256>>>();
    k4<<<2048, 256>>>(x, adj, P_l, P_w, out);
}

// round 13
// speedup vs baseline: 1.0696x; 1.0524x over previous
#include <cuda_runtime.h>
#include <cuda_fp16.h>
#include <math.h>

#define BB   16
#define NN   1024
#define HH   4
#define KDIM 128
#define FO   64
#define COLS 256
#define ALPHA 0.2f
#define L2E   1.44269504088896340736f
#define MAXNZ 160

// Static device scratch
__device__ __half g_hh4[BB*NN*COLS];   // h fp16, lane-interleaved for k4, 8 MB
// layout: halfs [row][lane(0..31)][h(0..3)][po(0..1)], value = h[row][h*64 + po*32 + lane]
__device__ float4 g_f1q[BB*NN], g_f2q[BB*NN];   // per-(b,n) head-packed f1/f2
__device__ float4 g_part[8][BB*NN];
__device__ float4 g_invq[BB*NN];
__device__ int    g_done[BB*4];        // per (b, jt) arrival counters (zero-init)

__device__ __forceinline__ float ex2f(float x) {
    float y; asm("ex2.approx.f32 %0, %1;" : "=f"(y) : "f"(x)); return y;
}
__device__ __forceinline__ void ffma2(unsigned long long& d,
                                      unsigned long long a, unsigned long long b) {
    asm("fma.rn.f32x2 %0, %1, %2, %0;" : "+l"(d) : "l"(a), "l"(b));
}
__device__ __forceinline__ float2 unpk(unsigned long long p) {
    float2 r;
    asm("mov.b64 {%0, %1}, %2;" : "=f"(r.x), "=f"(r.y) : "l"(p));
    return r;
}

// ---------------------------------------------------------------------------
// K1: FFMA2 GEMM + fused f1/f2 reduction (unchanged R10 winner).
// ---------------------------------------------------------------------------
__global__ void __launch_bounds__(256, 1) k1_gemm(
        const float* __restrict__ x, const float* __restrict__ SE,
        const float* __restrict__ W,
        const float* __restrict__ a1, const float* __restrict__ a2) {
    __shared__ __align__(16) float As[128][36];
    __shared__ __align__(16) float Bs[64][36];
    const int rt = blockIdx.x, ct = blockIdx.y, tid = threadIdx.x;
    const int tx = tid & 15, ty = tid >> 4;

    unsigned long long acc[8][4];
#pragma unroll
    for (int r = 0; r < 8; r++)
#pragma unroll
        for (int c = 0; c < 4; c++) acc[r][c] = 0ull;

    for (int ch = 0; ch < 4; ch++) {
        const int kk = ch * 32;
#pragma unroll
        for (int r = 0; r < 4; r++) {
            int q = tid + r * 256;
            int m = q >> 3, kc = (q & 7) << 2;
            int nb = rt * 128 + m;
            const float* src = (kk < 64)
                ? (x  + (size_t)nb * 64 + kk + kc)
                : (SE + (size_t)(nb & 1023) * 64 + (kk - 64) + kc);
            *(float4*)&As[m][kc] = *(const float4*)src;
        }
#pragma unroll
        for (int r = 0; r < 2; r++) {
            int q = tid + r * 256;
            int c = q & 63, k4 = (q >> 6) << 2;
            float4 v;
            const float* wp = W + ((size_t)ct * KDIM + kk + k4) * FO + c;
            v.x = wp[0]; v.y = wp[FO]; v.z = wp[2 * FO]; v.w = wp[3 * FO];
            *(float4*)&Bs[c][k4] = v;
        }
        __syncthreads();
#pragma unroll
        for (int kq = 0; kq < 8; kq++) {
            ulonglong2 bq[4];
#pragma unroll
            for (int c = 0; c < 4; c++)
                bq[c] = *(const ulonglong2*)&Bs[tx + 16 * c][kq * 4];
#pragma unroll
            for (int r = 0; r < 8; r++) {
                ulonglong2 aq = *(const ulonglong2*)&As[ty * 8 + r][kq * 4];
#pragma unroll
                for (int c = 0; c < 4; c++) {
                    ffma2(acc[r][c], aq.x, bq[c].x);
                    ffma2(acc[r][c], aq.y, bq[c].y);
                }
            }
        }
        __syncthreads();
    }

    const int row0 = rt * 128 + ty * 8;
    const float A0 = a1[ct * FO + tx],      A1 = a1[ct * FO + tx + 16];
    const float A2 = a1[ct * FO + tx + 32], A3 = a1[ct * FO + tx + 48];
    const float B0 = a2[ct * FO + tx],      B1 = a2[ct * FO + tx + 16];
    const float B2 = a2[ct * FO + tx + 32], B3 = a2[ct * FO + tx + 48];
    float p1[8], p2[8];
#pragma unroll
    for (int r = 0; r < 8; r++) {
        float2 q0 = unpk(acc[r][0]);
        float2 q1 = unpk(acc[r][1]);
        float2 q2 = unpk(acc[r][2]);
        float2 q3 = unpk(acc[r][3]);
        float v0 = q0.x + q0.y;
        float v1 = q1.x + q1.y;
        float v2 = q2.x + q2.y;
        float v3 = q3.x + q3.y;
        size_t row = (size_t)(row0 + r);
        __half2* dst = (__half2*)(g_hh4 + row * COLS);
        dst[tx * 4 + ct]        = __floats2half2_rn(v0, v2);
        dst[(tx + 16) * 4 + ct] = __floats2half2_rn(v1, v3);
        p1[r] = v0 * A0 + v1 * A1 + v2 * A2 + v3 * A3;
        p2[r] = v0 * B0 + v1 * B1 + v2 * B2 + v3 * B3;
    }
#pragma unroll
    for (int mask = 1; mask < 16; mask <<= 1) {
#pragma unroll
        for (int r = 0; r < 8; r++) {
            p1[r] += __shfl_xor_sync(0xffffffffu, p1[r], mask);
            p2[r] += __shfl_xor_sync(0xffffffffu, p2[r], mask);
        }
    }
    if (tx == 0) {
#pragma unroll
        for (int r = 0; r < 8; r++) {
            ((float*)g_f1q)[(size_t)(row0 + r) * 4 + ct] = p1[r];
            ((float*)g_f2q)[(size_t)(row0 + r) * 4 + ct] = p2[r];
        }
    }
}

// ---------------------------------------------------------------------------
// K3 v3: partial column sums + FUSED finalize (last-block-done pattern).
// The 8th arriving ic-block of each (b,jt) tile reduces the 8 partials and
// writes g_invq, then resets the counter (safe across graph replays).
// ---------------------------------------------------------------------------
__global__ void k3(const float* __restrict__ P_l) {
    const int ic = blockIdx.x, jt = blockIdx.y, b = blockIdx.z;
    __shared__ float4 sf1[128], sar[128];
    __shared__ int s_old;
    const int tid = threadIdx.x;
    if (tid < 128) {
        sf1[tid] = g_f1q[b * NN + ic * 128 + tid];
    } else {
        int ii = tid - 128;
        float4 f1 = g_f1q[b * NN + ic * 128 + ii];
        float4 a;
        a.x = ALPHA * L2E * (P_l[0]*f1.x + P_l[4]*f1.y + P_l[8]*f1.z  + P_l[12]*f1.w);
        a.y = ALPHA * L2E * (P_l[1]*f1.x + P_l[5]*f1.y + P_l[9]*f1.z  + P_l[13]*f1.w);
        a.z = ALPHA * L2E * (P_l[2]*f1.x + P_l[6]*f1.y + P_l[10]*f1.z + P_l[14]*f1.w);
        a.w = ALPHA * L2E * (P_l[3]*f1.x + P_l[7]*f1.y + P_l[11]*f1.z + P_l[15]*f1.w);
        sar[ii] = a;
    }
    __syncthreads();

    const int j = jt * 256 + tid;
    const float4 f2 = g_f2q[b * NN + j];
    float c[16];
#pragma unroll
    for (int t = 0; t < 16; t++) c[t] = (1.f - ALPHA) * L2E * P_l[t];

    float s0 = 0.f, s1 = 0.f, s2 = 0.f, s3 = 0.f;
#pragma unroll 4
    for (int i = 0; i < 128; i++) {
        float4 f1 = sf1[i], ar = sar[i];
        float r0 = fmaxf(f1.x + f2.x, 0.f);
        float r1 = fmaxf(f1.y + f2.y, 0.f);
        float r2 = fmaxf(f1.z + f2.z, 0.f);
        float r3 = fmaxf(f1.w + f2.w, 0.f);
        float e0 = ar.x, e1 = ar.y, e2 = ar.z, e3 = ar.w;
        e0 = fmaf(c[0], r0, e0); e0 = fmaf(c[4], r1, e0); e0 = fmaf(c[8],  r2, e0); e0 = fmaf(c[12], r3, e0);
        e1 = fmaf(c[1], r0, e1); e1 = fmaf(c[5], r1, e1); e1 = fmaf(c[9],  r2, e1); e1 = fmaf(c[13], r3, e1);
        e2 = fmaf(c[2], r0, e2); e2 = fmaf(c[6], r1, e2); e2 = fmaf(c[10], r2, e2); e2 = fmaf(c[14], r3, e2);
        e3 = fmaf(c[3], r0, e3); e3 = fmaf(c[7], r1, e3); e3 = fmaf(c[11], r2, e3); e3 = fmaf(c[15], r3, e3);
        s0 += ex2f(e0); s1 += ex2f(e1); s2 += ex2f(e2); s3 += ex2f(e3);
    }
    g_part[ic][b * NN + j] = make_float4(s0, s1, s2, s3);

    // ---- fused finalize ----
    __threadfence();
    __syncthreads();
    if (tid == 0) s_old = atomicAdd(&g_done[b * 4 + jt], 1);
    __syncthreads();
    if (s_old == 7) {
        __threadfence();
        int bj = b * NN + jt * 256 + tid;
        float4 s = g_part[0][bj];
#pragma unroll
        for (int q = 1; q < 8; q++) {
            float4 p = g_part[q][bj];
            s.x += p.x; s.y += p.y; s.z += p.z; s.w += p.w;
        }
        g_invq[bj] = make_float4(1.f / s.x, 1.f / s.y, 1.f / s.z, 1.f / s.w);
        if (tid == 0) g_done[b * 4 + jt] = 0;   // reset for next graph replay
    }
}

// ---------------------------------------------------------------------------
// K4: EXACT R10 winner (47us). Phase A preloaded adj + register ballots;
// phase B reg constants; phase C interleaved fp16, 1 LDG.128/nnz, unroll 8.
// ---------------------------------------------------------------------------
__global__ void __launch_bounds__(256) k4(
        const float* __restrict__ x, const float* __restrict__ adj,
        const float* __restrict__ P_l, const float* __restrict__ P_w,
        float* __restrict__ out) {
    __shared__ int    sj[8][MAXNZ];
    __shared__ float4 sw[8][MAXNZ];
    const int ws   = threadIdx.x >> 5;
    const int lane = threadIdx.x & 31;
    const int gw   = blockIdx.x * 8 + ws;
    const int b = gw >> 10, i = gw & 1023;
    const int bN = b * NN;

    // Phase A: preload entire adj row (MLP 8), then register ballots
    const float* adjrow = adj + (size_t)(bN + i) * NN;
    float4 av[8];
#pragma unroll
    for (int q = 0; q < 8; q++)
        av[q] = *(const float4*)(adjrow + q * 128 + lane * 4);
    int base = 0;
#pragma unroll
    for (int q = 0; q < 8; q++) {
        float vv[4] = {av[q].x, av[q].y, av[q].z, av[q].w};
#pragma unroll
        for (int u = 0; u < 4; u++) {
            unsigned m = __ballot_sync(0xffffffffu, vv[u] != 0.f);
            if (vv[u] != 0.f) {
                int pos = base + __popc(m & ((1u << lane) - 1));
                if (pos < MAXNZ) sj[ws][pos] = q * 128 + lane * 4 + u;
            }
            base += __popc(m);
        }
    }
    int nnz = min(base, MAXNZ);
    __syncwarp();

    // Phase B: lane-parallel weights (ar computed from c and f1)
    {
        const float4 f1 = g_f1q[bN + i];
        float c[16], pw[16];
#pragma unroll
        for (int t = 0; t < 16; t++) { c[t] = (1.f - ALPHA) * L2E * P_l[t]; pw[t] = P_w[t]; }
        const float ar0 = 0.25f * (c[0]*f1.x + c[4]*f1.y + c[8]*f1.z  + c[12]*f1.w);
        const float ar1 = 0.25f * (c[1]*f1.x + c[5]*f1.y + c[9]*f1.z  + c[13]*f1.w);
        const float ar2 = 0.25f * (c[2]*f1.x + c[6]*f1.y + c[10]*f1.z + c[14]*f1.w);
        const float ar3 = 0.25f * (c[3]*f1.x + c[7]*f1.y + c[11]*f1.z + c[15]*f1.w);
        for (int t = lane; t < nnz; t += 32) {
            int j = sj[ws][t];
            float4 f2  = g_f2q[bN + j];
            float4 inv = g_invq[bN + j];
            float r0 = fmaxf(f1.x + f2.x, 0.f);
            float r1 = fmaxf(f1.y + f2.y, 0.f);
            float r2 = fmaxf(f1.z + f2.z, 0.f);
            float r3 = fmaxf(f1.w + f2.w, 0.f);
            float e0 = ar0, e1 = ar1, e2 = ar2, e3 = ar3;
            e0 = fmaf(c[0], r0, e0); e0 = fmaf(c[4], r1, e0); e0 = fmaf(c[8],  r2, e0); e0 = fmaf(c[12], r3, e0);
            e1 = fmaf(c[1], r0, e1); e1 = fmaf(c[5], r1, e1); e1 = fmaf(c[9],  r2, e1); e1 = fmaf(c[13], r3, e1);
            e2 = fmaf(c[2], r0, e2); e2 = fmaf(c[6], r1, e2); e2 = fmaf(c[10], r2, e2); e2 = fmaf(c[14], r3, e2);
            e3 = fmaf(c[3], r0, e3); e3 = fmaf(c[7], r1, e3); e3 = fmaf(c[11], r2, e3); e3 = fmaf(c[15], r3, e3);
            float x0 = ex2f(e0) * inv.x;
            float x1 = ex2f(e1) * inv.y;
            float x2 = ex2f(e2) * inv.z;
            float x3 = ex2f(e3) * inv.w;
            float w0 = pw[0]*x0 + pw[4]*x1 + pw[8]*x2  + pw[12]*x3;
            float w1 = pw[1]*x0 + pw[5]*x1 + pw[9]*x2  + pw[13]*x3;
            float w2 = pw[2]*x0 + pw[6]*x1 + pw[10]*x2 + pw[14]*x3;
            float w3 = pw[3]*x0 + pw[7]*x1 + pw[11]*x2 + pw[15]*x3;
            sw[ws][t] = make_float4(w0, w1, w2, w3);
        }
    }
    __syncwarp();

    // Phase C: interleaved fp16 gather, ONE LDG.128 per nnz, unroll 8
    float2 acc[4];
#pragma unroll
    for (int m = 0; m < 4; m++) acc[m] = make_float2(0.f, 0.f);

    const __half* hbase = g_hh4 + (size_t)bN * COLS + lane * 8;
    int t = 0;
    for (; t + 8 <= nnz; t += 8) {
#pragma unroll
        for (int u = 0; u < 8; u++) {
            int j = sj[ws][t + u];
            float4 w = sw[ws][t + u];
            uint4 u4 = *(const uint4*)(hbase + (size_t)j * COLS);
            float2 v0 = __half22float2(*(__half2*)&u4.x);
            float2 v1 = __half22float2(*(__half2*)&u4.y);
            float2 v2 = __half22float2(*(__half2*)&u4.z);
            float2 v3 = __half22float2(*(__half2*)&u4.w);
            acc[0].x = fmaf(w.x, v0.x, acc[0].x); acc[0].y = fmaf(w.x, v0.y, acc[0].y);
            acc[1].x = fmaf(w.y, v1.x, acc[1].x); acc[1].y = fmaf(w.y, v1.y, acc[1].y);
            acc[2].x = fmaf(w.z, v2.x, acc[2].x); acc[2].y = fmaf(w.z, v2.y, acc[2].y);
            acc[3].x = fmaf(w.w, v3.x, acc[3].x); acc[3].y = fmaf(w.w, v3.y, acc[3].y);
        }
    }
    for (; t < nnz; t++) {
        int j = sj[ws][t];
        float4 w = sw[ws][t];
        uint4 u4 = *(const uint4*)(hbase + (size_t)j * COLS);
        float2 v0 = __half22float2(*(__half2*)&u4.x);
        float2 v1 = __half22float2(*(__half2*)&u4.y);
        float2 v2 = __half22float2(*(__half2*)&u4.z);
        float2 v3 = __half22float2(*(__half2*)&u4.w);
        acc[0].x = fmaf(w.x, v0.x, acc[0].x); acc[0].y = fmaf(w.x, v0.y, acc[0].y);
        acc[1].x = fmaf(w.y, v1.x, acc[1].x); acc[1].y = fmaf(w.y, v1.y, acc[1].y);
        acc[2].x = fmaf(w.z, v2.x, acc[2].x); acc[2].y = fmaf(w.z, v2.y, acc[2].y);
        acc[3].x = fmaf(w.w, v3.x, acc[3].x); acc[3].y = fmaf(w.w, v3.y, acc[3].y);
    }

    // Epilogue: residual + ELU. acc[h] = (col h*64+lane, col h*64+32+lane).
    const float* xrow = x + (size_t)(bN + i) * FO;
    float xv0 = xrow[lane], xv1 = xrow[lane + 32];
    float* orow = out + (size_t)(bN + i) * COLS;
#pragma unroll
    for (int m = 0; m < 4; m++) {
        float z0 = acc[m].x + xv0;
        float z1 = acc[m].y + xv1;
        orow[m * 64 + lane]      = (z0 > 0.f) ? z0 : expm1f(z0);
        orow[m * 64 + 32 + lane] = (z1 > 0.f) ? z1 : expm1f(z1);
    }
}

extern "C" void kernel_launch(void* const* d_in, const int* in_sizes, int n_in,
                              void* d_out, int out_size) {
    const float* x   = (const float*)d_in[0];
    const float* adj = (const float*)d_in[1];
    const float* SE  = (const float*)d_in[2];
    const float* W   = (const float*)d_in[3];
    const float* a1  = (const float*)d_in[4];
    const float* a2  = (const float*)d_in[5];
    const float* P_l = (const float*)d_in[6];
    const float* P_w = (const float*)d_in[7];
    float* out = (float*)d_out;

    k1_gemm<<<dim3(128, 4), 256>>>(x, SE, W, a1, a2);
    k3<<<dim3(8, 4, 16), 256>>>(P_l);
    k4<<<2048, 256>>>(x, adj, P_l, P_w, out);
}

// round 14
// speedup vs baseline: 1.1300x; 1.0565x over previous
#include <cuda_runtime.h>
#include <cuda_fp16.h>
#include <math.h>

#define BB   16
#define NN   1024
#define HH   4
#define KDIM 128
#define FO   64
#define COLS 256
#define ALPHA 0.2f
#define L2E   1.44269504088896340736f
#define MAXNZ 160

// Static device scratch
__device__ __half g_hh4[BB*NN*COLS];   // h fp16, lane-interleaved for k4, 8 MB
// layout: halfs [row][lane(0..31)][h(0..3)][po(0..1)], value = h[row][h*64 + po*32 + lane]
__device__ float4 g_f1q[BB*NN], g_f2q[BB*NN];   // per-(b,n) head-packed f1/f2
__device__ float4 g_part[8][BB*NN];
__device__ float4 g_invq[BB*NN];

__device__ __forceinline__ float ex2f(float x) {
    float y; asm("ex2.approx.f32 %0, %1;" : "=f"(y) : "f"(x)); return y;
}
__device__ __forceinline__ void ffma2(unsigned long long& d,
                                      unsigned long long a, unsigned long long b) {
    asm("fma.rn.f32x2 %0, %1, %2, %0;" : "+l"(d) : "l"(a), "l"(b));
}
__device__ __forceinline__ float2 unpk(unsigned long long p) {
    float2 r;
    asm("mov.b64 {%0, %1}, %2;" : "=f"(r.x), "=f"(r.y) : "l"(p));
    return r;
}

// ---------------------------------------------------------------------------
// K1: FFMA2 GEMM + fused f1/f2 reduction. ONLY change vs R10: launch_bounds
// (256, 2) caps regs at 128 -> 2 blocks/SM (was 162 regs, 1 block/SM,
// issue 30%). Mainloop live set ~110 regs so no mainloop spills expected.
// ---------------------------------------------------------------------------
__global__ void __launch_bounds__(256, 2) k1_gemm(
        const float* __restrict__ x, const float* __restrict__ SE,
        const float* __restrict__ W,
        const float* __restrict__ a1, const float* __restrict__ a2) {
    __shared__ __align__(16) float As[128][36];
    __shared__ __align__(16) float Bs[64][36];
    const int rt = blockIdx.x, ct = blockIdx.y, tid = threadIdx.x;
    const int tx = tid & 15, ty = tid >> 4;

    unsigned long long acc[8][4];
#pragma unroll
    for (int r = 0; r < 8; r++)
#pragma unroll
        for (int c = 0; c < 4; c++) acc[r][c] = 0ull;

    for (int ch = 0; ch < 4; ch++) {
        const int kk = ch * 32;
#pragma unroll
        for (int r = 0; r < 4; r++) {
            int q = tid + r * 256;
            int m = q >> 3, kc = (q & 7) << 2;
            int nb = rt * 128 + m;
            const float* src = (kk < 64)
                ? (x  + (size_t)nb * 64 + kk + kc)
                : (SE + (size_t)(nb & 1023) * 64 + (kk - 64) + kc);
            *(float4*)&As[m][kc] = *(const float4*)src;
        }
#pragma unroll
        for (int r = 0; r < 2; r++) {
            int q = tid + r * 256;
            int c = q & 63, k4 = (q >> 6) << 2;
            float4 v;
            const float* wp = W + ((size_t)ct * KDIM + kk + k4) * FO + c;
            v.x = wp[0]; v.y = wp[FO]; v.z = wp[2 * FO]; v.w = wp[3 * FO];
            *(float4*)&Bs[c][k4] = v;
        }
        __syncthreads();
#pragma unroll
        for (int kq = 0; kq < 8; kq++) {
            ulonglong2 bq[4];
#pragma unroll
            for (int c = 0; c < 4; c++)
                bq[c] = *(const ulonglong2*)&Bs[tx + 16 * c][kq * 4];
#pragma unroll
            for (int r = 0; r < 8; r++) {
                ulonglong2 aq = *(const ulonglong2*)&As[ty * 8 + r][kq * 4];
#pragma unroll
                for (int c = 0; c < 4; c++) {
                    ffma2(acc[r][c], aq.x, bq[c].x);
                    ffma2(acc[r][c], aq.y, bq[c].y);
                }
            }
        }
        __syncthreads();
    }

    const int row0 = rt * 128 + ty * 8;
    const float A0 = a1[ct * FO + tx],      A1 = a1[ct * FO + tx + 16];
    const float A2 = a1[ct * FO + tx + 32], A3 = a1[ct * FO + tx + 48];
    const float B0 = a2[ct * FO + tx],      B1 = a2[ct * FO + tx + 16];
    const float B2 = a2[ct * FO + tx + 32], B3 = a2[ct * FO + tx + 48];
    float p1[8], p2[8];
#pragma unroll
    for (int r = 0; r < 8; r++) {
        float2 q0 = unpk(acc[r][0]);
        float2 q1 = unpk(acc[r][1]);
        float2 q2 = unpk(acc[r][2]);
        float2 q3 = unpk(acc[r][3]);
        float v0 = q0.x + q0.y;
        float v1 = q1.x + q1.y;
        float v2 = q2.x + q2.y;
        float v3 = q3.x + q3.y;
        size_t row = (size_t)(row0 + r);
        __half2* dst = (__half2*)(g_hh4 + row * COLS);
        dst[tx * 4 + ct]        = __floats2half2_rn(v0, v2);
        dst[(tx + 16) * 4 + ct] = __floats2half2_rn(v1, v3);
        p1[r] = v0 * A0 + v1 * A1 + v2 * A2 + v3 * A3;
        p2[r] = v0 * B0 + v1 * B1 + v2 * B2 + v3 * B3;
    }
#pragma unroll
    for (int mask = 1; mask < 16; mask <<= 1) {
#pragma unroll
        for (int r = 0; r < 8; r++) {
            p1[r] += __shfl_xor_sync(0xffffffffu, p1[r], mask);
            p2[r] += __shfl_xor_sync(0xffffffffu, p2[r], mask);
        }
    }
    if (tx == 0) {
#pragma unroll
        for (int r = 0; r < 8; r++) {
            ((float*)g_f1q)[(size_t)(row0 + r) * 4 + ct] = p1[r];
            ((float*)g_f2q)[(size_t)(row0 + r) * 4 + ct] = p2[r];
        }
    }
}

// ---------------------------------------------------------------------------
// K3: partial column sums (exact R10 form — no fence/fusion).
// ---------------------------------------------------------------------------
__global__ void k3(const float* __restrict__ P_l) {
    const int ic = blockIdx.x, jt = blockIdx.y, b = blockIdx.z;
    __shared__ float4 sf1[128], sar[128];
    const int tid = threadIdx.x;
    if (tid < 128) {
        sf1[tid] = g_f1q[b * NN + ic * 128 + tid];
    } else {
        int ii = tid - 128;
        float4 f1 = g_f1q[b * NN + ic * 128 + ii];
        float4 a;
        a.x = ALPHA * L2E * (P_l[0]*f1.x + P_l[4]*f1.y + P_l[8]*f1.z  + P_l[12]*f1.w);
        a.y = ALPHA * L2E * (P_l[1]*f1.x + P_l[5]*f1.y + P_l[9]*f1.z  + P_l[13]*f1.w);
        a.z = ALPHA * L2E * (P_l[2]*f1.x + P_l[6]*f1.y + P_l[10]*f1.z + P_l[14]*f1.w);
        a.w = ALPHA * L2E * (P_l[3]*f1.x + P_l[7]*f1.y + P_l[11]*f1.z + P_l[15]*f1.w);
        sar[ii] = a;
    }
    __syncthreads();

    const int j = jt * 256 + tid;
    const float4 f2 = g_f2q[b * NN + j];
    float c[16];
#pragma unroll
    for (int t = 0; t < 16; t++) c[t] = (1.f - ALPHA) * L2E * P_l[t];

    float s0 = 0.f, s1 = 0.f, s2 = 0.f, s3 = 0.f;
#pragma unroll 4
    for (int i = 0; i < 128; i++) {
        float4 f1 = sf1[i], ar = sar[i];
        float r0 = fmaxf(f1.x + f2.x, 0.f);
        float r1 = fmaxf(f1.y + f2.y, 0.f);
        float r2 = fmaxf(f1.z + f2.z, 0.f);
        float r3 = fmaxf(f1.w + f2.w, 0.f);
        float e0 = ar.x, e1 = ar.y, e2 = ar.z, e3 = ar.w;
        e0 = fmaf(c[0], r0, e0); e0 = fmaf(c[4], r1, e0); e0 = fmaf(c[8],  r2, e0); e0 = fmaf(c[12], r3, e0);
        e1 = fmaf(c[1], r0, e1); e1 = fmaf(c[5], r1, e1); e1 = fmaf(c[9],  r2, e1); e1 = fmaf(c[13], r3, e1);
        e2 = fmaf(c[2], r0, e2); e2 = fmaf(c[6], r1, e2); e2 = fmaf(c[10], r2, e2); e2 = fmaf(c[14], r3, e2);
        e3 = fmaf(c[3], r0, e3); e3 = fmaf(c[7], r1, e3); e3 = fmaf(c[11], r2, e3); e3 = fmaf(c[15], r3, e3);
        s0 += ex2f(e0); s1 += ex2f(e1); s2 += ex2f(e2); s3 += ex2f(e3);
    }
    g_part[ic][b * NN + j] = make_float4(s0, s1, s2, s3);
}

// K3b: serial reduce (R10 form)
__global__ void k3b() {
    int bj = blockIdx.x * 256 + threadIdx.x;
    float4 s = g_part[0][bj];
#pragma unroll
    for (int ic = 1; ic < 8; ic++) {
        float4 p = g_part[ic][bj];
        s.x += p.x; s.y += p.y; s.z += p.z; s.w += p.w;
    }
    g_invq[bj] = make_float4(1.f / s.x, 1.f / s.y, 1.f / s.z, 1.f / s.w);
}

// ---------------------------------------------------------------------------
// K4: EXACT R10 winner (47us), untouched.
// ---------------------------------------------------------------------------
__global__ void __launch_bounds__(256) k4(
        const float* __restrict__ x, const float* __restrict__ adj,
        const float* __restrict__ P_l, const float* __restrict__ P_w,
        float* __restrict__ out) {
    __shared__ int    sj[8][MAXNZ];
    __shared__ float4 sw[8][MAXNZ];
    const int ws   = threadIdx.x >> 5;
    const int lane = threadIdx.x & 31;
    const int gw   = blockIdx.x * 8 + ws;
    const int b = gw >> 10, i = gw & 1023;
    const int bN = b * NN;

    // Phase A: preload entire adj row (MLP 8), then register ballots
    const float* adjrow = adj + (size_t)(bN + i) * NN;
    float4 av[8];
#pragma unroll
    for (int q = 0; q < 8; q++)
        av[q] = *(const float4*)(adjrow + q * 128 + lane * 4);
    int base = 0;
#pragma unroll
    for (int q = 0; q < 8; q++) {
        float vv[4] = {av[q].x, av[q].y, av[q].z, av[q].w};
#pragma unroll
        for (int u = 0; u < 4; u++) {
            unsigned m = __ballot_sync(0xffffffffu, vv[u] != 0.f);
            if (vv[u] != 0.f) {
                int pos = base + __popc(m & ((1u << lane) - 1));
                if (pos < MAXNZ) sj[ws][pos] = q * 128 + lane * 4 + u;
            }
            base += __popc(m);
        }
    }
    int nnz = min(base, MAXNZ);
    __syncwarp();

    // Phase B: lane-parallel weights (ar computed from c and f1)
    {
        const float4 f1 = g_f1q[bN + i];
        float c[16], pw[16];
#pragma unroll
        for (int t = 0; t < 16; t++) { c[t] = (1.f - ALPHA) * L2E * P_l[t]; pw[t] = P_w[t]; }
        const float ar0 = 0.25f * (c[0]*f1.x + c[4]*f1.y + c[8]*f1.z  + c[12]*f1.w);
        const float ar1 = 0.25f * (c[1]*f1.x + c[5]*f1.y + c[9]*f1.z  + c[13]*f1.w);
        const float ar2 = 0.25f * (c[2]*f1.x + c[6]*f1.y + c[10]*f1.z + c[14]*f1.w);
        const float ar3 = 0.25f * (c[3]*f1.x + c[7]*f1.y + c[11]*f1.z + c[15]*f1.w);
        for (int t = lane; t < nnz; t += 32) {
            int j = sj[ws][t];
            float4 f2  = g_f2q[bN + j];
            float4 inv = g_invq[bN + j];
            float r0 = fmaxf(f1.x + f2.x, 0.f);
            float r1 = fmaxf(f1.y + f2.y, 0.f);
            float r2 = fmaxf(f1.z + f2.z, 0.f);
            float r3 = fmaxf(f1.w + f2.w, 0.f);
            float e0 = ar0, e1 = ar1, e2 = ar2, e3 = ar3;
            e0 = fmaf(c[0], r0, e0); e0 = fmaf(c[4], r1, e0); e0 = fmaf(c[8],  r2, e0); e0 = fmaf(c[12], r3, e0);
            e1 = fmaf(c[1], r0, e1); e1 = fmaf(c[5], r1, e1); e1 = fmaf(c[9],  r2, e1); e1 = fmaf(c[13], r3, e1);
            e2 = fmaf(c[2], r0, e2); e2 = fmaf(c[6], r1, e2); e2 = fmaf(c[10], r2, e2); e2 = fmaf(c[14], r3, e2);
            e3 = fmaf(c[3], r0, e3); e3 = fmaf(c[7], r1, e3); e3 = fmaf(c[11], r2, e3); e3 = fmaf(c[15], r3, e3);
            float x0 = ex2f(e0) * inv.x;
            float x1 = ex2f(e1) * inv.y;
            float x2 = ex2f(e2) * inv.z;
            float x3 = ex2f(e3) * inv.w;
            float w0 = pw[0]*x0 + pw[4]*x1 + pw[8]*x2  + pw[12]*x3;
            float w1 = pw[1]*x0 + pw[5]*x1 + pw[9]*x2  + pw[13]*x3;
            float w2 = pw[2]*x0 + pw[6]*x1 + pw[10]*x2 + pw[14]*x3;
            float w3 = pw[3]*x0 + pw[7]*x1 + pw[11]*x2 + pw[15]*x3;
            sw[ws][t] = make_float4(w0, w1, w2, w3);
        }
    }
    __syncwarp();

    // Phase C: interleaved fp16 gather, ONE LDG.128 per nnz, unroll 8
    float2 acc[4];
#pragma unroll
    for (int m = 0; m < 4; m++) acc[m] = make_float2(0.f, 0.f);

    const __half* hbase = g_hh4 + (size_t)bN * COLS + lane * 8;
    int t = 0;
    for (; t + 8 <= nnz; t += 8) {
#pragma unroll
        for (int u = 0; u < 8; u++) {
            int j = sj[ws][t + u];
            float4 w = sw[ws][t + u];
            uint4 u4 = *(const uint4*)(hbase + (size_t)j * COLS);
            float2 v0 = __half22float2(*(__half2*)&u4.x);
            float2 v1 = __half22float2(*(__half2*)&u4.y);
            float2 v2 = __half22float2(*(__half2*)&u4.z);
            float2 v3 = __half22float2(*(__half2*)&u4.w);
            acc[0].x = fmaf(w.x, v0.x, acc[0].x); acc[0].y = fmaf(w.x, v0.y, acc[0].y);
            acc[1].x = fmaf(w.y, v1.x, acc[1].x); acc[1].y = fmaf(w.y, v1.y, acc[1].y);
            acc[2].x = fmaf(w.z, v2.x, acc[2].x); acc[2].y = fmaf(w.z, v2.y, acc[2].y);
            acc[3].x = fmaf(w.w, v3.x, acc[3].x); acc[3].y = fmaf(w.w, v3.y, acc[3].y);
        }
    }
    for (; t < nnz; t++) {
        int j = sj[ws][t];
        float4 w = sw[ws][t];
        uint4 u4 = *(const uint4*)(hbase + (size_t)j * COLS);
        float2 v0 = __half22float2(*(__half2*)&u4.x);
        float2 v1 = __half22float2(*(__half2*)&u4.y);
        float2 v2 = __half22float2(*(__half2*)&u4.z);
        float2 v3 = __half22float2(*(__half2*)&u4.w);
        acc[0].x = fmaf(w.x, v0.x, acc[0].x); acc[0].y = fmaf(w.x, v0.y, acc[0].y);
        acc[1].x = fmaf(w.y, v1.x, acc[1].x); acc[1].y = fmaf(w.y, v1.y, acc[1].y);
        acc[2].x = fmaf(w.z, v2.x, acc[2].x); acc[2].y = fmaf(w.z, v2.y, acc[2].y);
        acc[3].x = fmaf(w.w, v3.x, acc[3].x); acc[3].y = fmaf(w.w, v3.y, acc[3].y);
    }

    // Epilogue: residual + ELU. acc[h] = (col h*64+lane, col h*64+32+lane).
    const float* xrow = x + (size_t)(bN + i) * FO;
    float xv0 = xrow[lane], xv1 = xrow[lane + 32];
    float* orow = out + (size_t)(bN + i) * COLS;
#pragma unroll
    for (int m = 0; m < 4; m++) {
        float z0 = acc[m].x + xv0;
        float z1 = acc[m].y + xv1;
        orow[m * 64 + lane]      = (z0 > 0.f) ? z0 : expm1f(z0);
        orow[m * 64 + 32 + lane] = (z1 > 0.f) ? z1 : expm1f(z1);
    }
}

extern "C" void kernel_launch(void* const* d_in, const int* in_sizes, int n_in,
                              void* d_out, int out_size) {
    const float* x   = (const float*)d_in[0];
    const float* adj = (const float*)d_in[1];
    const float* SE  = (const float*)d_in[2];
    const float* W   = (const float*)d_in[3];
    const float* a1  = (const float*)d_in[4];
    const float* a2  = (const float*)d_in[5];
    const float* P_l = (const float*)d_in[6];
    const float* P_w = (const float*)d_in[7];
    float* out = (float*)d_out;

    k1_gemm<<<dim3(128, 4), 256>>>(x, SE, W, a1, a2);
    k3<<<dim3(8, 4, 16), 256>>>(P_l);
    k3b<<<64, 256>>>();
    k4<<<2048, 256>>>(x, adj, P_l, P_w, out);
}

// round 15
// speedup vs baseline: 1.1516x; 1.0191x over previous
#include <cuda_runtime.h>
#include <cuda_fp16.h>
#include <math.h>

#define BB   16
#define NN   1024
#define HH   4
#define KDIM 128
#define FO   64
#define COLS 256
#define ALPHA 0.2f
#define L2E   1.44269504088896340736f
// lrelu(t) = C1*t + C2*|t|  with alpha=0.2  ->  C1=0.6, C2=0.4
#define CT    (0.6f * L2E)
#define CABS  (0.4f * L2E)
#define MAXNZ 160

// Static device scratch
__device__ __half g_hh4[BB*NN*COLS];   // h fp16, lane-interleaved for k4, 8 MB
// layout: halfs [row][lane(0..31)][h(0..3)][po(0..1)], value = h[row][h*64 + po*32 + lane]
__device__ float4 g_f1q[BB*NN], g_f2q[BB*NN];   // per-(b,n) head-packed f1/f2
__device__ float4 g_part[8][BB*NN];
__device__ float4 g_invq[BB*NN];

__device__ __forceinline__ float ex2f(float x) {
    float y; asm("ex2.approx.f32 %0, %1;" : "=f"(y) : "f"(x)); return y;
}
__device__ __forceinline__ void ffma2(unsigned long long& d,
                                      unsigned long long a, unsigned long long b) {
    asm("fma.rn.f32x2 %0, %1, %2, %0;" : "+l"(d) : "l"(a), "l"(b));
}
__device__ __forceinline__ float2 unpk(unsigned long long p) {
    float2 r;
    asm("mov.b64 {%0, %1}, %2;" : "=f"(r.x), "=f"(r.y) : "l"(p));
    return r;
}

// ---------------------------------------------------------------------------
// K1: FFMA2 GEMM + fused f1/f2 reduction (R14 winner, unchanged).
// ---------------------------------------------------------------------------
__global__ void __launch_bounds__(256, 2) k1_gemm(
        const float* __restrict__ x, const float* __restrict__ SE,
        const float* __restrict__ W,
        const float* __restrict__ a1, const float* __restrict__ a2) {
    __shared__ __align__(16) float As[128][36];
    __shared__ __align__(16) float Bs[64][36];
    const int rt = blockIdx.x, ct = blockIdx.y, tid = threadIdx.x;
    const int tx = tid & 15, ty = tid >> 4;

    unsigned long long acc[8][4];
#pragma unroll
    for (int r = 0; r < 8; r++)
#pragma unroll
        for (int c = 0; c < 4; c++) acc[r][c] = 0ull;

    for (int ch = 0; ch < 4; ch++) {
        const int kk = ch * 32;
#pragma unroll
        for (int r = 0; r < 4; r++) {
            int q = tid + r * 256;
            int m = q >> 3, kc = (q & 7) << 2;
            int nb = rt * 128 + m;
            const float* src = (kk < 64)
                ? (x  + (size_t)nb * 64 + kk + kc)
                : (SE + (size_t)(nb & 1023) * 64 + (kk - 64) + kc);
            *(float4*)&As[m][kc] = *(const float4*)src;
        }
#pragma unroll
        for (int r = 0; r < 2; r++) {
            int q = tid + r * 256;
            int c = q & 63, k4 = (q >> 6) << 2;
            float4 v;
            const float* wp = W + ((size_t)ct * KDIM + kk + k4) * FO + c;
            v.x = wp[0]; v.y = wp[FO]; v.z = wp[2 * FO]; v.w = wp[3 * FO];
            *(float4*)&Bs[c][k4] = v;
        }
        __syncthreads();
#pragma unroll
        for (int kq = 0; kq < 8; kq++) {
            ulonglong2 bq[4];
#pragma unroll
            for (int c = 0; c < 4; c++)
                bq[c] = *(const ulonglong2*)&Bs[tx + 16 * c][kq * 4];
#pragma unroll
            for (int r = 0; r < 8; r++) {
                ulonglong2 aq = *(const ulonglong2*)&As[ty * 8 + r][kq * 4];
#pragma unroll
                for (int c = 0; c < 4; c++) {
                    ffma2(acc[r][c], aq.x, bq[c].x);
                    ffma2(acc[r][c], aq.y, bq[c].y);
                }
            }
        }
        __syncthreads();
    }

    const int row0 = rt * 128 + ty * 8;
    const float A0 = a1[ct * FO + tx],      A1 = a1[ct * FO + tx + 16];
    const float A2 = a1[ct * FO + tx + 32], A3 = a1[ct * FO + tx + 48];
    const float B0 = a2[ct * FO + tx],      B1 = a2[ct * FO + tx + 16];
    const float B2 = a2[ct * FO + tx + 32], B3 = a2[ct * FO + tx + 48];
    float p1[8], p2[8];
#pragma unroll
    for (int r = 0; r < 8; r++) {
        float2 q0 = unpk(acc[r][0]);
        float2 q1 = unpk(acc[r][1]);
        float2 q2 = unpk(acc[r][2]);
        float2 q3 = unpk(acc[r][3]);
        float v0 = q0.x + q0.y;
        float v1 = q1.x + q1.y;
        float v2 = q2.x + q2.y;
        float v3 = q3.x + q3.y;
        size_t row = (size_t)(row0 + r);
        __half2* dst = (__half2*)(g_hh4 + row * COLS);
        dst[tx * 4 + ct]        = __floats2half2_rn(v0, v2);
        dst[(tx + 16) * 4 + ct] = __floats2half2_rn(v1, v3);
        p1[r] = v0 * A0 + v1 * A1 + v2 * A2 + v3 * A3;
        p2[r] = v0 * B0 + v1 * B1 + v2 * B2 + v3 * B3;
    }
#pragma unroll
    for (int mask = 1; mask < 16; mask <<= 1) {
#pragma unroll
        for (int r = 0; r < 8; r++) {
            p1[r] += __shfl_xor_sync(0xffffffffu, p1[r], mask);
            p2[r] += __shfl_xor_sync(0xffffffffu, p2[r], mask);
        }
    }
    if (tx == 0) {
#pragma unroll
        for (int r = 0; r < 8; r++) {
            ((float*)g_f1q)[(size_t)(row0 + r) * 4 + ct] = p1[r];
            ((float*)g_f2q)[(size_t)(row0 + r) * 4 + ct] = p2[r];
        }
    }
}

// ---------------------------------------------------------------------------
// K3 v4: abs-form exponent (no fmax in the inner loop).
// e_g = [CT*(P^T f1)_g](i) + CABS*sum_h P[h,g]*|f1_h(i)+f2_h(j)|
// (the j-separable CT-term cancels in the softmax over i)
// ---------------------------------------------------------------------------
__global__ void k3(const float* __restrict__ P_l) {
    const int ic = blockIdx.x, jt = blockIdx.y, b = blockIdx.z;
    __shared__ float4 sf1[128], sar[128];
    const int tid = threadIdx.x;
    if (tid < 128) {
        sf1[tid] = g_f1q[b * NN + ic * 128 + tid];
    } else {
        int ii = tid - 128;
        float4 f1 = g_f1q[b * NN + ic * 128 + ii];
        float4 a;
        a.x = CT * (P_l[0]*f1.x + P_l[4]*f1.y + P_l[8]*f1.z  + P_l[12]*f1.w);
        a.y = CT * (P_l[1]*f1.x + P_l[5]*f1.y + P_l[9]*f1.z  + P_l[13]*f1.w);
        a.z = CT * (P_l[2]*f1.x + P_l[6]*f1.y + P_l[10]*f1.z + P_l[14]*f1.w);
        a.w = CT * (P_l[3]*f1.x + P_l[7]*f1.y + P_l[11]*f1.z + P_l[15]*f1.w);
        sar[ii] = a;
    }
    __syncthreads();

    const int j = jt * 256 + tid;
    const float4 f2 = g_f2q[b * NN + j];
    float c[16];
#pragma unroll
    for (int t = 0; t < 16; t++) c[t] = CABS * P_l[t];

    float s0 = 0.f, s1 = 0.f, s2 = 0.f, s3 = 0.f;
#pragma unroll 4
    for (int i = 0; i < 128; i++) {
        float4 f1 = sf1[i], ar = sar[i];
        float r0 = fabsf(f1.x + f2.x);
        float r1 = fabsf(f1.y + f2.y);
        float r2 = fabsf(f1.z + f2.z);
        float r3 = fabsf(f1.w + f2.w);
        float e0 = ar.x, e1 = ar.y, e2 = ar.z, e3 = ar.w;
        e0 = fmaf(c[0], r0, e0); e0 = fmaf(c[4], r1, e0); e0 = fmaf(c[8],  r2, e0); e0 = fmaf(c[12], r3, e0);
        e1 = fmaf(c[1], r0, e1); e1 = fmaf(c[5], r1, e1); e1 = fmaf(c[9],  r2, e1); e1 = fmaf(c[13], r3, e1);
        e2 = fmaf(c[2], r0, e2); e2 = fmaf(c[6], r1, e2); e2 = fmaf(c[10], r2, e2); e2 = fmaf(c[14], r3, e2);
        e3 = fmaf(c[3], r0, e3); e3 = fmaf(c[7], r1, e3); e3 = fmaf(c[11], r2, e3); e3 = fmaf(c[15], r3, e3);
        s0 += ex2f(e0); s1 += ex2f(e1); s2 += ex2f(e2); s3 += ex2f(e3);
    }
    g_part[ic][b * NN + j] = make_float4(s0, s1, s2, s3);
}

// K3b: serial reduce; grid reshaped 64x256 -> 128x128 for SM spread
__global__ void k3b() {
    int bj = blockIdx.x * 128 + threadIdx.x;
    float4 s = g_part[0][bj];
#pragma unroll
    for (int ic = 1; ic < 8; ic++) {
        float4 p = g_part[ic][bj];
        s.x += p.x; s.y += p.y; s.z += p.z; s.w += p.w;
    }
    g_invq[bj] = make_float4(1.f / s.x, 1.f / s.y, 1.f / s.z, 1.f / s.w);
}

// ---------------------------------------------------------------------------
// K4: R10 structure; phase B uses the abs-form exponent (matches k3).
// ar_g = CT*(P^T f1)_g = 1.5 * (c^T f1)_g  since c = CABS*P and CT/CABS = 1.5.
// ---------------------------------------------------------------------------
__global__ void __launch_bounds__(256) k4(
        const float* __restrict__ x, const float* __restrict__ adj,
        const float* __restrict__ P_l, const float* __restrict__ P_w,
        float* __restrict__ out) {
    __shared__ int    sj[8][MAXNZ];
    __shared__ float4 sw[8][MAXNZ];
    const int ws   = threadIdx.x >> 5;
    const int lane = threadIdx.x & 31;
    const int gw   = blockIdx.x * 8 + ws;
    const int b = gw >> 10, i = gw & 1023;
    const int bN = b * NN;

    // Phase A: preload entire adj row (MLP 8), then register ballots
    const float* adjrow = adj + (size_t)(bN + i) * NN;
    float4 av[8];
#pragma unroll
    for (int q = 0; q < 8; q++)
        av[q] = *(const float4*)(adjrow + q * 128 + lane * 4);
    int base = 0;
#pragma unroll
    for (int q = 0; q < 8; q++) {
        float vv[4] = {av[q].x, av[q].y, av[q].z, av[q].w};
#pragma unroll
        for (int u = 0; u < 4; u++) {
            unsigned m = __ballot_sync(0xffffffffu, vv[u] != 0.f);
            if (vv[u] != 0.f) {
                int pos = base + __popc(m & ((1u << lane) - 1));
                if (pos < MAXNZ) sj[ws][pos] = q * 128 + lane * 4 + u;
            }
            base += __popc(m);
        }
    }
    int nnz = min(base, MAXNZ);
    __syncwarp();

    // Phase B: lane-parallel weights (abs-form exponent)
    {
        const float4 f1 = g_f1q[bN + i];
        float c[16], pw[16];
#pragma unroll
        for (int t = 0; t < 16; t++) { c[t] = CABS * P_l[t]; pw[t] = P_w[t]; }
        const float ar0 = 1.5f * (c[0]*f1.x + c[4]*f1.y + c[8]*f1.z  + c[12]*f1.w);
        const float ar1 = 1.5f * (c[1]*f1.x + c[5]*f1.y + c[9]*f1.z  + c[13]*f1.w);
        const float ar2 = 1.5f * (c[2]*f1.x + c[6]*f1.y + c[10]*f1.z + c[14]*f1.w);
        const float ar3 = 1.5f * (c[3]*f1.x + c[7]*f1.y + c[11]*f1.z + c[15]*f1.w);
        for (int t = lane; t < nnz; t += 32) {
            int j = sj[ws][t];
            float4 f2  = g_f2q[bN + j];
            float4 inv = g_invq[bN + j];
            float r0 = fabsf(f1.x + f2.x);
            float r1 = fabsf(f1.y + f2.y);
            float r2 = fabsf(f1.z + f2.z);
            float r3 = fabsf(f1.w + f2.w);
            float e0 = ar0, e1 = ar1, e2 = ar2, e3 = ar3;
            e0 = fmaf(c[0], r0, e0); e0 = fmaf(c[4], r1, e0); e0 = fmaf(c[8],  r2, e0); e0 = fmaf(c[12], r3, e0);
            e1 = fmaf(c[1], r0, e1); e1 = fmaf(c[5], r1, e1); e1 = fmaf(c[9],  r2, e1); e1 = fmaf(c[13], r3, e1);
            e2 = fmaf(c[2], r0, e2); e2 = fmaf(c[6], r1, e2); e2 = fmaf(c[10], r2, e2); e2 = fmaf(c[14], r3, e2);
            e3 = fmaf(c[3], r0, e3); e3 = fmaf(c[7], r1, e3); e3 = fmaf(c[11], r2, e3); e3 = fmaf(c[15], r3, e3);
            float x0 = ex2f(e0) * inv.x;
            float x1 = ex2f(e1) * inv.y;
            float x2 = ex2f(e2) * inv.z;
            float x3 = ex2f(e3) * inv.w;
            float w0 = pw[0]*x0 + pw[4]*x1 + pw[8]*x2  + pw[12]*x3;
            float w1 = pw[1]*x0 + pw[5]*x1 + pw[9]*x2  + pw[13]*x3;
            float w2 = pw[2]*x0 + pw[6]*x1 + pw[10]*x2 + pw[14]*x3;
            float w3 = pw[3]*x0 + pw[7]*x1 + pw[11]*x2 + pw[15]*x3;
            sw[ws][t] = make_float4(w0, w1, w2, w3);
        }
    }
    __syncwarp();

    // Phase C: interleaved fp16 gather, ONE LDG.128 per nnz, unroll 8
    float2 acc[4];
#pragma unroll
    for (int m = 0; m < 4; m++) acc[m] = make_float2(0.f, 0.f);

    const __half* hbase = g_hh4 + (size_t)bN * COLS + lane * 8;
    int t = 0;
    for (; t + 8 <= nnz; t += 8) {
#pragma unroll
        for (int u = 0; u < 8; u++) {
            int j = sj[ws][t + u];
            float4 w = sw[ws][t + u];
            uint4 u4 = *(const uint4*)(hbase + (size_t)j * COLS);
            float2 v0 = __half22float2(*(__half2*)&u4.x);
            float2 v1 = __half22float2(*(__half2*)&u4.y);
            float2 v2 = __half22float2(*(__half2*)&u4.z);
            float2 v3 = __half22float2(*(__half2*)&u4.w);
            acc[0].x = fmaf(w.x, v0.x, acc[0].x); acc[0].y = fmaf(w.x, v0.y, acc[0].y);
            acc[1].x = fmaf(w.y, v1.x, acc[1].x); acc[1].y = fmaf(w.y, v1.y, acc[1].y);
            acc[2].x = fmaf(w.z, v2.x, acc[2].x); acc[2].y = fmaf(w.z, v2.y, acc[2].y);
            acc[3].x = fmaf(w.w, v3.x, acc[3].x); acc[3].y = fmaf(w.w, v3.y, acc[3].y);
        }
    }
    for (; t < nnz; t++) {
        int j = sj[ws][t];
        float4 w = sw[ws][t];
        uint4 u4 = *(const uint4*)(hbase + (size_t)j * COLS);
        float2 v0 = __half22float2(*(__half2*)&u4.x);
        float2 v1 = __half22float2(*(__half2*)&u4.y);
        float2 v2 = __half22float2(*(__half2*)&u4.z);
        float2 v3 = __half22float2(*(__half2*)&u4.w);
        acc[0].x = fmaf(w.x, v0.x, acc[0].x); acc[0].y = fmaf(w.x, v0.y, acc[0].y);
        acc[1].x = fmaf(w.y, v1.x, acc[1].x); acc[1].y = fmaf(w.y, v1.y, acc[1].y);
        acc[2].x = fmaf(w.z, v2.x, acc[2].x); acc[2].y = fmaf(w.z, v2.y, acc[2].y);
        acc[3].x = fmaf(w.w, v3.x, acc[3].x); acc[3].y = fmaf(w.w, v3.y, acc[3].y);
    }

    // Epilogue: residual + ELU. acc[h] = (col h*64+lane, col h*64+32+lane).
    const float* xrow = x + (size_t)(bN + i) * FO;
    float xv0 = xrow[lane], xv1 = xrow[lane + 32];
    float* orow = out + (size_t)(bN + i) * COLS;
#pragma unroll
    for (int m = 0; m < 4; m++) {
        float z0 = acc[m].x + xv0;
        float z1 = acc[m].y + xv1;
        orow[m * 64 + lane]      = (z0 > 0.f) ? z0 : expm1f(z0);
        orow[m * 64 + 32 + lane] = (z1 > 0.f) ? z1 : expm1f(z1);
    }
}

extern "C" void kernel_launch(void* const* d_in, const int* in_sizes, int n_in,
                              void* d_out, int out_size) {
    const float* x   = (const float*)d_in[0];
    const float* adj = (const float*)d_in[1];
    const float* SE  = (const float*)d_in[2];
    const float* W   = (const float*)d_in[3];
    const float* a1  = (const float*)d_in[4];
    const float* a2  = (const float*)d_in[5];
    const float* P_l = (const float*)d_in[6];
    const float* P_w = (const float*)d_in[7];
    float* out = (float*)d_out;

    k1_gemm<<<dim3(128, 4), 256>>>(x, SE, W, a1, a2);
    k3<<<dim3(8, 4, 16), 256>>>(P_l);
    k3b<<<128, 128>>>();
    k4<<<2048, 256>>>(x, adj, P_l, P_w, out);
}